// round 16
// baseline (speedup 1.0000x reference)
#include <cuda_runtime.h>
#include <cuda_fp16.h>
#include <mma.h>
using namespace nvcuda;

#define NTOKEN 150000
#define NEDGE  2400000
#define NPAIR  (NEDGE / 2)
#define NBLK   148
#define NTHR   512
#define GSZ    (NBLK * NTHR)
#define NWARPS (GSZ / 32)
#define NTILES ((NTOKEN + 63) / 64)   // 2344 matvec tiles

// ---------------- scratch (static __device__, no allocation) ----------------
__device__ int    g_is64;
__device__ int    g_deg[NTOKEN];
__device__ int    g_off[NTOKEN];
__device__ float  g_dinv[NTOKEN];
__device__ int    g_rank[NEDGE];
__device__ int    g_srcs[NEDGE];
__device__ __half g_Y2h[(size_t)NTOKEN * 64];  // 32  * dinv[v] * (emb[v] @ Wc)
__device__ __half g_g2h[(size_t)NTOKEN * 64];  // 1024* dinv[v] * h2[v]
__device__ float  g_Wc[64 * 64];               // W1 @ W2 (k row, c col)
__device__ float  g_bc[64];                    // b1 @ W2
__device__ int    g_bsum[NBLK];
__device__ unsigned     g_bar_count;           // zero-init; self-resets
__device__ volatile int g_bar_sense;           // zero-init; even #barriers -> ends 0

// Sense-reversing global barrier. All NBLK blocks are co-resident (1/SM).
__device__ __forceinline__ void gbar(int ls) {
    __syncthreads();
    if (threadIdx.x == 0) {
        __threadfence();
        unsigned prev = atomicAdd(&g_bar_count, 1);
        if (prev == NBLK - 1) {
            g_bar_count = 0;
            __threadfence();
            g_bar_sense = ls;
        } else {
            while (g_bar_sense != ls) __nanosleep(64);
            __threadfence();
        }
    }
    __syncthreads();
}
#define GBAR() do { sense ^= 1; gbar(sense); } while (0)

extern "C" __global__ void __launch_bounds__(NTHR, 1)
mega_kernel(const void* __restrict__ edge, const float* __restrict__ emb,
            const float* __restrict__ W1, const float* __restrict__ b1,
            const float* __restrict__ W2, const float* __restrict__ b2,
            const void* __restrict__ input, float* __restrict__ out, int npos) {
    __shared__ __align__(16) char SM[26624];
    int t = threadIdx.x, b = blockIdx.x;
    int gid = b * NTHR + t;
    int sense = 0;

    // ---------- P0: zero deg + detect is64 + Wc/bc ----------
    for (int i = gid; i < NTOKEN / 4; i += GSZ)
        ((int4*)g_deg)[i] = make_int4(0, 0, 0, 0);
    if (b == 0 && t < 32) {
        const unsigned long long* e = (const unsigned long long*)edge;
        int bad = ((e[t] >> 32) != 0ull) || ((e[t + 32] >> 32) != 0ull);
        unsigned m = __ballot_sync(0xffffffffu, bad);
        if (t == 0) g_is64 = (m == 0u) ? 1 : 0;
    }
    if (gid < 64 * 64) {
        int i = gid >> 6, j = gid & 63;
        float s = 0.0f;
#pragma unroll 8
        for (int k = 0; k < 128; k++) s += W1[i * 128 + k] * W2[k * 64 + j];
        g_Wc[gid] = s;
    } else if (gid < 64 * 64 + 64) {
        int j = gid - 64 * 64;
        float s = 0.0f;
#pragma unroll 8
        for (int k = 0; k < 128; k++) s += b1[k] * W2[k * 64 + j];
        g_bc[j] = s;
    }
    GBAR();  // 1

    // ---------- P1: count + rank (2 edges/thread, wide loads) ----------
    int is64 = g_is64;
    if (is64) {
        const int4* e = (const int4*)((const long long*)edge + NEDGE);
        for (long long p = gid; p < NPAIR; p += GSZ) {
            int4 w = e[p];
            g_rank[p * 2]     = atomicAdd(&g_deg[w.x], 1);
            g_rank[p * 2 + 1] = atomicAdd(&g_deg[w.z], 1);
        }
    } else {
        const int2* e = (const int2*)((const int*)edge + NEDGE);
        for (long long p = gid; p < NPAIR; p += GSZ) {
            int2 w = e[p];
            g_rank[p * 2]     = atomicAdd(&g_deg[w.x], 1);
            g_rank[p * 2 + 1] = atomicAdd(&g_deg[w.y], 1);
        }
    }
    GBAR();  // 2

    // ---------- P2a: block-local scan (1024 elems/block), publish sums ----------
    int* s1 = (int*)SM;                        // 512 ints
    int base = b * 1024;
    int i0 = base + t * 2;
    int d0 = (i0 < NTOKEN) ? g_deg[i0] : 0;
    int d1 = (i0 + 1 < NTOKEN) ? g_deg[i0 + 1] : 0;
    s1[t] = d0 + d1;
    __syncthreads();
    for (int off = 1; off < NTHR; off <<= 1) {
        int u = (t >= off) ? s1[t - off] : 0;
        __syncthreads();
        s1[t] += u;
        __syncthreads();
    }
    int incl_pair = s1[t];                     // inclusive over pairs 0..t
    if (t == NTHR - 1) g_bsum[b] = incl_pair;
    GBAR();  // 3

    // ---------- P2b: cross-block offsets + emit off/dinv ----------
    {
        int* sred = (int*)(SM + 2048);
        int val = 0;
        for (int j = t; j < b; j += NTHR) val += g_bsum[j];
        sred[t] = val;
        __syncthreads();
        for (int off = NTHR / 2; off > 0; off >>= 1) {
            if (t < off) sred[t] += sred[t + off];
            __syncthreads();
        }
        int boff = sred[0];
        int e0 = boff + incl_pair - d0 - d1;
        if (i0 < NTOKEN)     { g_off[i0] = e0;          g_dinv[i0] = rsqrtf((float)d0 + 1.0f); }
        if (i0 + 1 < NTOKEN) { g_off[i0 + 1] = e0 + d0; g_dinv[i0 + 1] = rsqrtf((float)d1 + 1.0f); }
    }
    GBAR();  // 4

    // ---------- P3: atomic-free scatter ----------
    if (is64) {
        const int4* es = (const int4*)edge;
        const int4* ed = (const int4*)((const long long*)edge + NEDGE);
        for (long long p = gid; p < NPAIR; p += GSZ) {
            int4 ws = es[p], wd = ed[p];
            int2 r = ((const int2*)g_rank)[p];
            g_srcs[g_off[wd.x] + r.x] = ws.x;
            g_srcs[g_off[wd.z] + r.y] = ws.z;
        }
    } else {
        const int2* es = (const int2*)edge;
        const int2* ed = (const int2*)((const int*)edge + NEDGE);
        for (long long p = gid; p < NPAIR; p += GSZ) {
            int2 ws = es[p], wd = ed[p];
            int2 r = ((const int2*)g_rank)[p];
            g_srcs[g_off[wd.x] + r.x] = ws.x;
            g_srcs[g_off[wd.y] + r.y] = ws.y;
        }
    }
    GBAR();  // 5

    // ---------- P4: wmma matvec: Y2h = fp16(dinv * (emb_h @ (32Wc)_h)) ----------
    {
        __half* sB = (__half*)SM;                       // 64x72 half (9216 B)
        char*   uni = SM + 9216;                        // union: sA (9216) / sC (16384)
        __half* sA = (__half*)uni;
        float*  sC = (float*)uni;
        float*  sD = (float*)(SM + 9216 + 16384);       // 64 floats
        for (int idx = t; idx < 2048; idx += NTHR) {
            int k = idx >> 5, c2 = idx & 31;
            float2 f = ((const float2*)g_Wc)[k * 32 + c2];
            *(__half2*)&sB[k * 72 + c2 * 2] = __floats2half2_rn(32.0f * f.x, 32.0f * f.y);
        }
        __syncthreads();
        int warp = t >> 5;
        for (int tile = b; tile < NTILES; tile += NBLK) {
            int node0 = tile * 64;
            for (int idx = t; idx < 2048; idx += NTHR) {
                int r = idx >> 5, c2 = idx & 31;
                int v = node0 + r;
                float2 f = (v < NTOKEN) ? ((const float2*)(emb + (size_t)v * 64))[c2]
                                        : make_float2(0.f, 0.f);
                *(__half2*)&sA[r * 72 + c2 * 2] = __floats2half2_rn(f.x, f.y);
            }
            if (t < 64) { int v = node0 + t; sD[t] = (v < NTOKEN) ? g_dinv[v] : 0.0f; }
            __syncthreads();
            wmma::fragment<wmma::accumulator, 16, 16, 16, float> fC;
            int tr = (warp >> 2) * 16, tc = (warp & 3) * 16;
            if (warp < 16) {
                wmma::fill_fragment(fC, 0.0f);
#pragma unroll
                for (int kk = 0; kk < 4; kk++) {
                    wmma::fragment<wmma::matrix_a, 16, 16, 16, __half, wmma::row_major> fA;
                    wmma::fragment<wmma::matrix_b, 16, 16, 16, __half, wmma::row_major> fB;
                    wmma::load_matrix_sync(fA, &sA[tr * 72 + kk * 16], 72);
                    wmma::load_matrix_sync(fB, &sB[(kk * 16) * 72 + tc], 72);
                    wmma::mma_sync(fC, fA, fB, fC);
                }
            }
            __syncthreads();                            // sA reads done; sC may overwrite
            if (warp < 16)
                wmma::store_matrix_sync(&sC[tr * 64 + tc], fC, 64, wmma::mem_row_major);
            __syncthreads();
            for (int idx = t; idx < 2048; idx += NTHR) {
                int r = idx >> 5, c2 = idx & 31;
                int v = node0 + r;
                if (v < NTOKEN) {
                    float dv = sD[r];
                    float2 f = ((const float2*)sC)[r * 32 + c2];
                    ((__half2*)(g_Y2h + (size_t)v * 64))[c2] =
                        __floats2half2_rn(dv * f.x, dv * f.y);
                }
            }
            __syncthreads();
        }
    }
    GBAR();  // 6

    // ---------- P5: agg: g2h[v] = 32*dv*dv*accS + 1024*dv*bc ----------
    int gw = gid >> 5, lane = t & 31;
    for (int v = gw; v < NTOKEN; v += NWARPS) {
        float dv = g_dinv[v];
        float2 acc = __half22float2(((const __half2*)(g_Y2h + (size_t)v * 64))[lane]);
        int o = g_off[v];
        int d = g_deg[v];
        int j = 0;
        for (; j + 3 < d; j += 4) {
            int s0 = g_srcs[o + j], s1i = g_srcs[o + j + 1];
            int s2 = g_srcs[o + j + 2], s3 = g_srcs[o + j + 3];
            float2 y0 = __half22float2(((const __half2*)(g_Y2h + (size_t)s0 * 64))[lane]);
            float2 y1 = __half22float2(((const __half2*)(g_Y2h + (size_t)s1i * 64))[lane]);
            float2 y2 = __half22float2(((const __half2*)(g_Y2h + (size_t)s2 * 64))[lane]);
            float2 y3 = __half22float2(((const __half2*)(g_Y2h + (size_t)s3 * 64))[lane]);
            acc.x += y0.x + y1.x + y2.x + y3.x;
            acc.y += y0.y + y1.y + y2.y + y3.y;
        }
        for (; j < d; j++) {
            int s = g_srcs[o + j];
            float2 y = __half22float2(((const __half2*)(g_Y2h + (size_t)s * 64))[lane]);
            acc.x += y.x; acc.y += y.y;
        }
        float2 bc = ((const float2*)g_bc)[lane];
        float k1 = 32.0f * dv * dv;
        float k2 = 1024.0f * dv;
        ((__half2*)(g_g2h + (size_t)v * 64))[lane] =
            __floats2half2_rn(k1 * acc.x + k2 * bc.x, k1 * acc.y + k2 * bc.y);
    }
    GBAR();  // 7

    // ---------- P6: out[pos] = dv*accG/1024 + b2 ----------
    {
        int st = is64 ? 2 : 1;
        const int* inp = (const int*)input;
        for (int w = gw; w < npos; w += NWARPS) {
            int v = inp[(long long)w * st];
            float dv = g_dinv[v];
            float2 acc = __half22float2(((const __half2*)(g_g2h + (size_t)v * 64))[lane]);
            int o = g_off[v];
            int d = g_deg[v];
            int j = 0;
            for (; j + 3 < d; j += 4) {
                int s0 = g_srcs[o + j], s1i = g_srcs[o + j + 1];
                int s2 = g_srcs[o + j + 2], s3 = g_srcs[o + j + 3];
                float2 y0 = __half22float2(((const __half2*)(g_g2h + (size_t)s0 * 64))[lane]);
                float2 y1 = __half22float2(((const __half2*)(g_g2h + (size_t)s1i * 64))[lane]);
                float2 y2 = __half22float2(((const __half2*)(g_g2h + (size_t)s2 * 64))[lane]);
                float2 y3 = __half22float2(((const __half2*)(g_g2h + (size_t)s3 * 64))[lane]);
                acc.x += y0.x + y1.x + y2.x + y3.x;
                acc.y += y0.y + y1.y + y2.y + y3.y;
            }
            for (; j < d; j++) {
                int s = g_srcs[o + j];
                float2 ys = __half22float2(((const __half2*)(g_g2h + (size_t)s * 64))[lane]);
                acc.x += ys.x; acc.y += ys.y;
            }
            float2 bb = ((const float2*)b2)[lane];
            float inv = dv * (1.0f / 1024.0f);
            float2 r;
            r.x = inv * acc.x + bb.x;
            r.y = inv * acc.y + bb.y;
            ((float2*)(out + (size_t)w * 64))[lane] = r;
        }
    }
    GBAR();  // 8 (even count -> barrier sense self-resets for next replay)
}

extern "C" void kernel_launch(void* const* d_in, const int* in_sizes, int n_in,
                              void* d_out, int out_size) {
    const float* emb = (const float*)d_in[0];
    const float* W1  = (const float*)d_in[1];
    const float* b1  = (const float*)d_in[2];
    const float* W2  = (const float*)d_in[3];
    const float* b2  = (const float*)d_in[4];
    const void*  input = d_in[5];
    const void*  edge  = d_in[7];
    float* out = (float*)d_out;
    int npos = in_sizes[5];  // B*L = 12800

    // Single persistent kernel: ONE graph node, zero launch gaps.
    mega_kernel<<<NBLK, NTHR>>>(edge, emb, W1, b1, W2, b2, input, out, npos);
}

// round 17
// speedup vs baseline: 1.5253x; 1.5253x over previous
#include <cuda_runtime.h>
#include <cuda_fp16.h>
#include <mma.h>
using namespace nvcuda;

#define NTOKEN 150000
#define NEDGE  2400000
#define NPAIR  (NEDGE / 2)
#define NSCANB ((NTOKEN + 255) / 256)   // 586 scan tiles
#define MVBLK  ((NTOKEN + 63) / 64)     // 2344 matvec tiles
#define NMARKW ((NTOKEN + 31) / 32)     // mark bitset words

// ---------------- scratch (static __device__, no allocation) ----------------
__device__ int           g_is64;
__device__ int           g_deg[NTOKEN];
__device__ int           g_off[NTOKEN];
__device__ float         g_dinv[NTOKEN];
__device__ unsigned      g_rank2[NPAIR];        // two u16 ranks per edge pair
__device__ int           g_srcs[NEDGE];         // CSR: src ids grouped by dst
__device__ unsigned      g_markbits[NMARKW];    // input nodes (bitset)
__device__ unsigned char g_need[NTOKEN];        // src of an edge into a marked node
__device__ __half        g_Y2h[(size_t)NTOKEN * 64];  // 32  * dinv * (emb @ Wc)
__device__ __half        g_g2h[(size_t)NTOKEN * 64];  // 1024* dinv * h2
__device__ float         g_Wc[64 * 64];         // W1 @ W2 (k row, c col)
__device__ float         g_bc[64];              // b1 @ W2
__device__ int           g_bsum[NSCANB];

// Fused prep: zero deg/markbits/need (blocks 0-146, grid-stride int4),
// Wc/bc matmul (blocks 148-163), int64 detection (block 0 warp 0).
__global__ void prep_kernel(const void* __restrict__ edge,
                            const float* __restrict__ W1,
                            const float* __restrict__ b1,
                            const float* __restrict__ W2) {
    int b = blockIdx.x, t = threadIdx.x;
    if (b < 147) {
        int gid = b * 256 + t;
        for (int i = gid; i < NTOKEN / 4; i += 147 * 256)
            ((int4*)g_deg)[i] = make_int4(0, 0, 0, 0);
        for (int i = gid; i < NMARKW; i += 147 * 256) g_markbits[i] = 0u;
        for (int i = gid; i < NTOKEN / 4; i += 147 * 256)
            ((unsigned*)g_need)[i] = 0u;        // NTOKEN/4 u32 words = NTOKEN bytes
        if (b == 0 && t < 32) {
            const unsigned long long* e = (const unsigned long long*)edge;
            int bad = ((e[t] >> 32) != 0ull) || ((e[t + 32] >> 32) != 0ull);
            unsigned m = __ballot_sync(0xffffffffu, bad);
            if (t == 0) g_is64 = (m == 0u) ? 1 : 0;
        }
    } else if (b >= 148) {
        int idx = (b - 148) * 256 + t;          // 0..4095
        int i = idx >> 6, j = idx & 63;         // k row, c col
        float s = 0.0f;
#pragma unroll 8
        for (int k = 0; k < 128; k++) s += W1[i * 128 + k] * W2[k * 64 + j];
        g_Wc[i * 64 + j] = s;
        if (b == 148 && t < 64) {
            float bb = 0.0f;
#pragma unroll 8
            for (int k = 0; k < 128; k++) bb += b1[k] * W2[k * 64 + t];
            g_bc[t] = bb;
        }
    }
}

// Count + rank (packed u16 pair) + mark input nodes (first npos threads).
__global__ void count_rank_kernel(const void* __restrict__ edge,
                                  const void* __restrict__ input, int npos) {
    long long p = (long long)blockIdx.x * blockDim.x + threadIdx.x;  // pair idx
    int is64 = g_is64;
    if (p < npos) {
        const int* inp = (const int*)input;
        int v = inp[p * (is64 ? 2 : 1)];
        atomicOr(&g_markbits[v >> 5], 1u << (v & 31));
    }
    if (p * 2 >= NEDGE) return;
    unsigned r0, r1;
    if (is64) {
        const int4* e = (const int4*)((const long long*)edge + NEDGE);
        int4 w = e[p];                        // dsts (low words x, z)
        r0 = (unsigned)atomicAdd(&g_deg[w.x], 1);
        r1 = (unsigned)atomicAdd(&g_deg[w.z], 1);
    } else {
        const int2* e = (const int2*)((const int*)edge + NEDGE);
        int2 w = e[p];
        r0 = (unsigned)atomicAdd(&g_deg[w.x], 1);
        r1 = (unsigned)atomicAdd(&g_deg[w.y], 1);
    }
    g_rank2[p] = r0 | (r1 << 16);
}

// scan1: per-tile degree sums + dinv.
__global__ void scan1_kernel() {
    __shared__ int sh[256];
    int t = threadIdx.x;
    int i = blockIdx.x * 256 + t;
    int d = (i < NTOKEN) ? g_deg[i] : 0;
    if (i < NTOKEN) g_dinv[i] = rsqrtf((float)d + 1.0f);
    sh[t] = d;
    __syncthreads();
    for (int off = 128; off > 0; off >>= 1) {
        if (t < off) sh[t] += sh[t + off];
        __syncthreads();
    }
    if (t == 0) g_bsum[blockIdx.x] = sh[0];
}

// scan3: tile offset from g_bsum (L2-hot) + local exclusive scan -> g_off.
__global__ void scan3_kernel() {
    __shared__ int sh[256];
    __shared__ int sboff;
    int t = threadIdx.x;
    int partial = 0;
    for (int i = t; i < blockIdx.x; i += 256) partial += g_bsum[i];
    sh[t] = partial;
    __syncthreads();
    for (int off = 128; off > 0; off >>= 1) {
        if (t < off) sh[t] += sh[t + off];
        __syncthreads();
    }
    if (t == 0) sboff = sh[0];
    __syncthreads();
    int i = blockIdx.x * 256 + t;
    int d = (i < NTOKEN) ? g_deg[i] : 0;
    sh[t] = d;
    __syncthreads();
    for (int off = 1; off < 256; off <<= 1) {
        int u = (t >= off) ? sh[t - off] : 0;
        __syncthreads();
        sh[t] += u;
        __syncthreads();
    }
    if (i < NTOKEN) g_off[i] = sh[t] - d + sboff;
}

// Atomic-free scatter + need-propagation: pos = off[dst] + rank.
__global__ void scatter_kernel(const void* __restrict__ edge) {
    long long p = (long long)blockIdx.x * blockDim.x + threadIdx.x;
    if (p * 2 >= NEDGE) return;
    int s0, s1, d0, d1;
    if (g_is64) {
        const int4* es = (const int4*)edge;
        const int4* ed = (const int4*)((const long long*)edge + NEDGE);
        int4 ws = es[p], wd = ed[p];
        s0 = ws.x; s1 = ws.z; d0 = wd.x; d1 = wd.z;
    } else {
        const int2* es = (const int2*)edge;
        const int2* ed = (const int2*)((const int*)edge + NEDGE);
        int2 ws = es[p], wd = ed[p];
        s0 = ws.x; s1 = ws.y; d0 = wd.x; d1 = wd.y;
    }
    unsigned rr = g_rank2[p];
    g_srcs[g_off[d0] + (int)(rr & 0xffffu)] = s0;
    g_srcs[g_off[d1] + (int)(rr >> 16)] = s1;
    // need[s] if dst is a marked (input) node — bitset reads stay L2-resident
    if (g_markbits[d0 >> 5] & (1u << (d0 & 31))) g_need[s0] = 1;
    if (g_markbits[d1 >> 5] & (1u << (d1 & 31))) g_need[s1] = 1;
}

// Tensor-core matvec: Y2h[v] = fp16( dinv[v] * (emb_h[v] @ (32*Wc)_h) ).
__global__ void matvec_kernel(const float* __restrict__ emb) {
    __shared__ __half sA[64 * 72];
    __shared__ __half sB[64 * 72];
    __shared__ float  sC[64 * 64];
    __shared__ float  sD[64];
    int tid = threadIdx.x;
    int node0 = blockIdx.x * 64;

    for (int idx = tid; idx < 2048; idx += 256) {
        int r = idx >> 5, c2 = idx & 31;
        int v = node0 + r;
        float2 f = (v < NTOKEN) ? ((const float2*)(emb + (size_t)v * 64))[c2]
                                : make_float2(0.f, 0.f);
        *(__half2*)&sA[r * 72 + c2 * 2] = __floats2half2_rn(f.x, f.y);
    }
    for (int idx = tid; idx < 2048; idx += 256) {
        int k = idx >> 5, c2 = idx & 31;
        float2 f = ((const float2*)g_Wc)[k * 32 + c2];
        *(__half2*)&sB[k * 72 + c2 * 2] = __floats2half2_rn(32.0f * f.x, 32.0f * f.y);
    }
    if (tid < 64) {
        int v = node0 + tid;
        sD[tid] = (v < NTOKEN) ? g_dinv[v] : 0.0f;
    }
    __syncthreads();

    int warp = tid >> 5;
#pragma unroll
    for (int rep = 0; rep < 2; rep++) {
        int tile = warp + rep * 8;
        int tr = (tile >> 2) * 16, tc = (tile & 3) * 16;
        wmma::fragment<wmma::accumulator, 16, 16, 16, float> fC;
        wmma::fill_fragment(fC, 0.0f);
#pragma unroll
        for (int kk = 0; kk < 4; kk++) {
            wmma::fragment<wmma::matrix_a, 16, 16, 16, __half, wmma::row_major> fA;
            wmma::fragment<wmma::matrix_b, 16, 16, 16, __half, wmma::row_major> fB;
            wmma::load_matrix_sync(fA, &sA[tr * 72 + kk * 16], 72);
            wmma::load_matrix_sync(fB, &sB[(kk * 16) * 72 + tc], 72);
            wmma::mma_sync(fC, fA, fB, fC);
        }
        wmma::store_matrix_sync(&sC[tr * 64 + tc], fC, 64, wmma::mem_row_major);
    }
    __syncthreads();

    for (int idx = tid; idx < 2048; idx += 256) {
        int r = idx >> 5, c2 = idx & 31;
        int v = node0 + r;
        if (v < NTOKEN) {
            float dv = sD[r];
            float2 f = ((const float2*)sC)[r * 32 + c2];
            ((__half2*)(g_Y2h + (size_t)v * 64))[c2] =
                __floats2half2_rn(dv * f.x, dv * f.y);
        }
    }
}

// Demand-driven agg: only nodes read by out (marked or needed).
// g2h[v] = 32*dv*dv*accS + 1024*dv*bc   (accS = 32x-scaled fp32 accumulation)
__global__ void agg_kernel() {
    int v = (blockIdx.x * blockDim.x + threadIdx.x) >> 5;
    int lane = threadIdx.x & 31;
    if (v >= NTOKEN) return;
    bool wanted = g_need[v] ||
                  (g_markbits[v >> 5] & (1u << (v & 31)));
    if (!wanted) return;
    float dv = g_dinv[v];
    float2 acc = __half22float2(((const __half2*)(g_Y2h + (size_t)v * 64))[lane]);
    int o = g_off[v];
    int d = g_deg[v];
    int j = 0;
    for (; j + 3 < d; j += 4) {
        int s0 = g_srcs[o + j], s1 = g_srcs[o + j + 1];
        int s2 = g_srcs[o + j + 2], s3 = g_srcs[o + j + 3];
        float2 y0 = __half22float2(((const __half2*)(g_Y2h + (size_t)s0 * 64))[lane]);
        float2 y1 = __half22float2(((const __half2*)(g_Y2h + (size_t)s1 * 64))[lane]);
        float2 y2 = __half22float2(((const __half2*)(g_Y2h + (size_t)s2 * 64))[lane]);
        float2 y3 = __half22float2(((const __half2*)(g_Y2h + (size_t)s3 * 64))[lane]);
        acc.x += y0.x + y1.x + y2.x + y3.x;
        acc.y += y0.y + y1.y + y2.y + y3.y;
    }
    for (; j < d; j++) {
        int s = g_srcs[o + j];
        float2 y = __half22float2(((const __half2*)(g_Y2h + (size_t)s * 64))[lane]);
        acc.x += y.x; acc.y += y.y;
    }
    float2 bc = ((const float2*)g_bc)[lane];
    float k1 = 32.0f * dv * dv;
    float k2 = 1024.0f * dv;
    ((__half2*)(g_g2h + (size_t)v * 64))[lane] =
        __floats2half2_rn(k1 * acc.x + k2 * bc.x, k1 * acc.y + k2 * bc.y);
}

// out[pos] = dv*accG/1024 + b2
__global__ void out_kernel(const void* __restrict__ input, const float* __restrict__ b2,
                           float* __restrict__ out, int npos) {
    int st = g_is64 ? 2 : 1;
    const int* inp = (const int*)input;
    int w = (blockIdx.x * blockDim.x + threadIdx.x) >> 5;
    int lane = threadIdx.x & 31;
    if (w >= npos) return;
    int v = inp[(long long)w * st];
    float dv = g_dinv[v];
    float2 acc = __half22float2(((const __half2*)(g_g2h + (size_t)v * 64))[lane]);
    int o = g_off[v];
    int d = g_deg[v];
    int j = 0;
    for (; j + 3 < d; j += 4) {
        int s0 = g_srcs[o + j], s1 = g_srcs[o + j + 1];
        int s2 = g_srcs[o + j + 2], s3 = g_srcs[o + j + 3];
        float2 y0 = __half22float2(((const __half2*)(g_g2h + (size_t)s0 * 64))[lane]);
        float2 y1 = __half22float2(((const __half2*)(g_g2h + (size_t)s1 * 64))[lane]);
        float2 y2 = __half22float2(((const __half2*)(g_g2h + (size_t)s2 * 64))[lane]);
        float2 y3 = __half22float2(((const __half2*)(g_g2h + (size_t)s3 * 64))[lane]);
        acc.x += y0.x + y1.x + y2.x + y3.x;
        acc.y += y0.y + y1.y + y2.y + y3.y;
    }
    for (; j < d; j++) {
        int s = g_srcs[o + j];
        float2 ys = __half22float2(((const __half2*)(g_g2h + (size_t)s * 64))[lane]);
        acc.x += ys.x; acc.y += ys.y;
    }
    float2 b = ((const float2*)b2)[lane];
    float inv = dv * (1.0f / 1024.0f);
    float2 r;
    r.x = inv * acc.x + b.x;
    r.y = inv * acc.y + b.y;
    ((float2*)(out + (size_t)w * 64))[lane] = r;
}

extern "C" void kernel_launch(void* const* d_in, const int* in_sizes, int n_in,
                              void* d_out, int out_size) {
    const float* emb = (const float*)d_in[0];
    const float* W1  = (const float*)d_in[1];
    const float* b1  = (const float*)d_in[2];
    const float* W2  = (const float*)d_in[3];
    const float* b2  = (const float*)d_in[4];
    const void*  input = d_in[5];
    const void*  edge  = d_in[7];
    float* out = (float*)d_out;
    int npos = in_sizes[5];  // B*L = 12800

    // Pure serial, single stream: 8 graph nodes.
    prep_kernel<<<164, 256>>>(edge, W1, b1, W2);
    count_rank_kernel<<<(NPAIR + 255) / 256, 256>>>(edge, input, npos);
    scan1_kernel<<<NSCANB, 256>>>();
    scan3_kernel<<<NSCANB, 256>>>();
    scatter_kernel<<<(NPAIR + 255) / 256, 256>>>(edge);
    matvec_kernel<<<MVBLK, 256>>>(emb);
    agg_kernel<<<(NTOKEN * 32 + 255) / 256, 256>>>();
    out_kernel<<<(npos * 32 + 255) / 256, 256>>>(input, b2, out, npos);
}